// round 3
// baseline (speedup 1.0000x reference)
#include <cuda_runtime.h>
#include <cstddef>

#define NTOK (8*128*128)   // 131072 tokens
#define DMODEL 128

// ---------------- scratch (static device memory: allocation-free) ----------------
__device__ float g_QKV[(size_t)NTOK * 768];   // [tok][ q0|k0|v0 | q1|k1|v1 ] 402MB
__device__ float g_O  [(size_t)NTOK * 256];   // [tok][ o0(128) | o1(128) ]   134MB
__device__ float g_Wcat [128 * 768];          // [k][ Wq0|Wk0|Wv0|Wq1|Wk1|Wv1 ]
__device__ float g_WoCat[256 * 128];          // [ Wo0 ; Wo1 ]
__device__ float g_bcat [128];                // bo0 + bo1

// ---------------- K0: pack weights ----------------
__global__ void pack_weights(const float* __restrict__ Wq0, const float* __restrict__ Wkv0,
                             const float* __restrict__ Wo0, const float* __restrict__ bo0,
                             const float* __restrict__ Wq1, const float* __restrict__ Wkv1,
                             const float* __restrict__ Wo1, const float* __restrict__ bo1) {
    const int n1 = 128 * 768;
    const int n2 = 256 * 128;
    for (int idx = blockIdx.x * blockDim.x + threadIdx.x; idx < n1 + n2 + 128;
         idx += gridDim.x * blockDim.x) {
        if (idx < n1) {
            int r = idx / 768, c = idx % 768;
            float v;
            if (c < 128)      v = Wq0 [r * 128 + c];
            else if (c < 384) v = Wkv0[r * 256 + (c - 128)];
            else if (c < 512) v = Wq1 [r * 128 + (c - 384)];
            else              v = Wkv1[r * 256 + (c - 512)];
            g_Wcat[idx] = v;
        } else if (idx < n1 + n2) {
            int j = idx - n1;
            int r = j / 128, c = j % 128;
            g_WoCat[j] = (r < 128) ? Wo0[r * 128 + c] : Wo1[(r - 128) * 128 + c];
        } else {
            int c = idx - n1 - n2;
            g_bcat[c] = bo0[c] + bo1[c];
        }
    }
}

// ---------------- SGEMM: C[M,N] = A[M,K] @ B[K,N] (+bias) ----------------
// BM=BN=128, BK=32, 256 threads, 8x8 register tile per thread.
// grid = (N/128, M/128). All dims are exact multiples here.
__global__ __launch_bounds__(256)
void sgemm_kernel(const float* __restrict__ A, const float* __restrict__ B,
                  float* __restrict__ C, int N, int K, const float* __restrict__ bias) {
    __shared__ __align__(16) float As[32][132];  // A^T chunk: [k][m]
    __shared__ __align__(16) float Bs[32][132];  // B chunk:   [k][n]

    const int t  = threadIdx.x;
    const int tx = t & 15;        // n-tile  (16 * 8 = 128 cols)
    const int ty = t >> 4;        // m-tile  (16 * 8 = 128 rows)
    const int nt = blockIdx.x, mt = blockIdx.y;

    const float* Ag = A + (size_t)mt * 128 * K;
    const float* Bg = B + (size_t)nt * 128;

    float acc[8][8] = {};

    for (int k0 = 0; k0 < K; k0 += 32) {
        // load A 128x32 chunk, transposed into As[k][m]
        #pragma unroll
        for (int l = 0; l < 4; l++) {
            int idx = t + l * 256;            // 0..1023
            int r = idx >> 3;                 // row 0..127
            int c4 = idx & 7;                 // float4 col 0..7
            float4 v = *(const float4*)(Ag + (size_t)r * K + k0 + c4 * 4);
            int kk = c4 * 4;
            As[kk + 0][r] = v.x; As[kk + 1][r] = v.y;
            As[kk + 2][r] = v.z; As[kk + 3][r] = v.w;
        }
        // load B 32x128 chunk
        #pragma unroll
        for (int l = 0; l < 4; l++) {
            int idx = t + l * 256;
            int r = idx >> 5;                 // 0..31
            int c4 = idx & 31;                // 0..31
            *(float4*)&Bs[r][c4 * 4] = *(const float4*)(Bg + (size_t)(k0 + r) * N + c4 * 4);
        }
        __syncthreads();

        #pragma unroll
        for (int kk = 0; kk < 32; kk++) {
            float4 a0 = *(const float4*)&As[kk][ty * 8];
            float4 a1 = *(const float4*)&As[kk][ty * 8 + 4];
            float4 b0 = *(const float4*)&Bs[kk][tx * 8];
            float4 b1 = *(const float4*)&Bs[kk][tx * 8 + 4];
            float av[8] = {a0.x, a0.y, a0.z, a0.w, a1.x, a1.y, a1.z, a1.w};
            float bv[8] = {b0.x, b0.y, b0.z, b0.w, b1.x, b1.y, b1.z, b1.w};
            #pragma unroll
            for (int i = 0; i < 8; i++)
                #pragma unroll
                for (int j = 0; j < 8; j++)
                    acc[i][j] += av[i] * bv[j];
        }
        __syncthreads();
    }

    float bv[8];
    #pragma unroll
    for (int j = 0; j < 8; j++) bv[j] = bias ? bias[nt * 128 + tx * 8 + j] : 0.f;

    #pragma unroll
    for (int i = 0; i < 8; i++) {
        size_t row = (size_t)mt * 128 + ty * 8 + i;
        float* cp = C + row * N + nt * 128 + tx * 8;
        *(float4*)(cp)     = make_float4(acc[i][0] + bv[0], acc[i][1] + bv[1],
                                         acc[i][2] + bv[2], acc[i][3] + bv[3]);
        *(float4*)(cp + 4) = make_float4(acc[i][4] + bv[4], acc[i][5] + bv[5],
                                         acc[i][6] + bv[6], acc[i][7] + bv[7]);
    }
}

// ---------------- K2: attention per (sequence, head, pass) ----------------
// grid = (1024, 8, 2), 256 threads, dynamic smem 95232 B.
// smem floats: QT[16][132] | KT[16][132] | VS[128][20] | PS[128][132] | RS[128]
#define SM_QT 0
#define SM_KT 2112
#define SM_VS 4224
#define SM_PS 6784
#define SM_RS 23680
#define SM_TOTAL_FLOATS 23808

__global__ void attn_kernel(const float* __restrict__ QKV, float* __restrict__ O) {
    extern __shared__ __align__(16) float sm[];
    float* QT = sm + SM_QT;
    float* KT = sm + SM_KT;
    float* VS = sm + SM_VS;
    float* PS = sm + SM_PS;
    float* RS = sm + SM_RS;

    const int t = threadIdx.x;
    const int s = blockIdx.x;     // sequence id (b*128 + other-axis)
    const int h = blockIdx.y;     // head
    const int p = blockIdx.z;     // pass: 0 = attend along H, 1 = attend along W
    const int b = s >> 7, sw = s & 127;
    const int coff = p * 384 + h * 16;

    // ---- load q, k, v (each 128x16) ----
    #pragma unroll
    for (int l = 0; l < 2; l++) {
        int idx = t + l * 256;            // 0..511
        int r = idx >> 2;                 // token 0..127
        int c4 = idx & 3;                 // float4 within 16
        size_t tok = p ? ((size_t)s * 128 + r)
                       : ((size_t)b * 16384 + (size_t)r * 128 + sw);
        const float* base = QKV + tok * 768 + coff;
        float4 q4 = *(const float4*)(base + c4 * 4);
        float4 k4 = *(const float4*)(base + 128 + c4 * 4);
        float4 v4 = *(const float4*)(base + 256 + c4 * 4);
        int e = c4 * 4;
        QT[(e + 0) * 132 + r] = q4.x; QT[(e + 1) * 132 + r] = q4.y;
        QT[(e + 2) * 132 + r] = q4.z; QT[(e + 3) * 132 + r] = q4.w;
        KT[(e + 0) * 132 + r] = k4.x; KT[(e + 1) * 132 + r] = k4.y;
        KT[(e + 2) * 132 + r] = k4.z; KT[(e + 3) * 132 + r] = k4.w;
        *(float4*)&VS[r * 20 + e] = v4;
    }
    __syncthreads();

    // ---- scores: 8x8 register tile of the 128x128 score matrix ----
    const int tx = t & 15, ty = t >> 4;
    const int i0 = ty * 8, j0 = tx * 8;
    float sc[8][8] = {};
    #pragma unroll
    for (int e = 0; e < 16; e++) {
        float4 a0 = *(const float4*)&QT[e * 132 + i0];
        float4 a1 = *(const float4*)&QT[e * 132 + i0 + 4];
        float4 b0 = *(const float4*)&KT[e * 132 + j0];
        float4 b1 = *(const float4*)&KT[e * 132 + j0 + 4];
        float av[8] = {a0.x, a0.y, a0.z, a0.w, a1.x, a1.y, a1.z, a1.w};
        float bv[8] = {b0.x, b0.y, b0.z, b0.w, b1.x, b1.y, b1.z, b1.w};
        #pragma unroll
        for (int i = 0; i < 8; i++)
            #pragma unroll
            for (int j = 0; j < 8; j++)
                sc[i][j] += av[i] * bv[j];
    }
    #pragma unroll
    for (int i = 0; i < 8; i++)
        #pragma unroll
        for (int j = 0; j < 8; j++)
            sc[i][j] *= 0.25f;   // e^-0.5, e=16

    // all QT/KT reads complete before PS writes (enables future smem overlay)
    __syncthreads();

    // ---- softmax over rows (reduce across the 16 tx-lanes; xor<=8 stays in-half) ----
    #pragma unroll
    for (int r = 0; r < 8; r++) {
        float mx = sc[r][0];
        #pragma unroll
        for (int j = 1; j < 8; j++) mx = fmaxf(mx, sc[r][j]);
        #pragma unroll
        for (int off = 8; off >= 1; off >>= 1)
            mx = fmaxf(mx, __shfl_xor_sync(0xffffffffu, mx, off));
        float sum = 0.f;
        #pragma unroll
        for (int j = 0; j < 8; j++) {
            float ev = __expf(sc[r][j] - mx);
            sc[r][j] = ev;
            sum += ev;
        }
        #pragma unroll
        for (int off = 8; off >= 1; off >>= 1)
            sum += __shfl_xor_sync(0xffffffffu, sum, off);
        if (tx == 0) RS[i0 + r] = sum;
        *(float4*)&PS[(i0 + r) * 132 + j0]     = make_float4(sc[r][0], sc[r][1], sc[r][2], sc[r][3]);
        *(float4*)&PS[(i0 + r) * 132 + j0 + 4] = make_float4(sc[r][4], sc[r][5], sc[r][6], sc[r][7]);
    }
    __syncthreads();

    // ---- PV: o[128][16] = P @ V, thread owns 2 rows x 4 cols ----
    const int e4 = t & 3, ig = t >> 2;
    const int ii = ig * 2, ee = e4 * 4;
    float o0[4] = {0.f, 0.f, 0.f, 0.f};
    float o1[4] = {0.f, 0.f, 0.f, 0.f};
    #pragma unroll 4
    for (int j = 0; j < 128; j += 4) {
        float4 p0 = *(const float4*)&PS[ii * 132 + j];
        float4 p1 = *(const float4*)&PS[(ii + 1) * 132 + j];
        float4 vv[4];
        vv[0] = *(const float4*)&VS[(j + 0) * 20 + ee];
        vv[1] = *(const float4*)&VS[(j + 1) * 20 + ee];
        vv[2] = *(const float4*)&VS[(j + 2) * 20 + ee];
        vv[3] = *(const float4*)&VS[(j + 3) * 20 + ee];
        float pr0[4] = {p0.x, p0.y, p0.z, p0.w};
        float pr1[4] = {p1.x, p1.y, p1.z, p1.w};
        #pragma unroll
        for (int k = 0; k < 4; k++) {
            const float* vp = (const float*)&vv[k];
            #pragma unroll
            for (int c = 0; c < 4; c++) {
                o0[c] += pr0[k] * vp[c];
                o1[c] += pr1[k] * vp[c];
            }
        }
    }
    float inv0 = 1.f / RS[ii];
    float inv1 = 1.f / RS[ii + 1];
    size_t tok0 = p ? ((size_t)s * 128 + ii)
                    : ((size_t)b * 16384 + (size_t)ii * 128 + sw);
    size_t tok1 = tok0 + (p ? 1 : 128);
    int ocol = p * 128 + h * 16 + ee;
    *(float4*)(O + tok0 * 256 + ocol) =
        make_float4(o0[0] * inv0, o0[1] * inv0, o0[2] * inv0, o0[3] * inv0);
    *(float4*)(O + tok1 * 256 + ocol) =
        make_float4(o1[0] * inv1, o1[1] * inv1, o1[2] * inv1, o1[3] * inv1);
}

// ---------------- launch ----------------
extern "C" void kernel_launch(void* const* d_in, const int* in_sizes, int n_in,
                              void* d_out, int out_size) {
    const float* x    = (const float*)d_in[0];
    const float* Wq0  = (const float*)d_in[1];
    const float* Wkv0 = (const float*)d_in[2];
    const float* Wo0  = (const float*)d_in[3];
    const float* bo0  = (const float*)d_in[4];
    const float* Wq1  = (const float*)d_in[5];
    const float* Wkv1 = (const float*)d_in[6];
    const float* Wo1  = (const float*)d_in[7];
    const float* bo1  = (const float*)d_in[8];
    float* out = (float*)d_out;

    void *pQKV, *pO, *pWcat, *pWoCat, *pbcat;
    cudaGetSymbolAddress(&pQKV,   g_QKV);
    cudaGetSymbolAddress(&pO,     g_O);
    cudaGetSymbolAddress(&pWcat,  g_Wcat);
    cudaGetSymbolAddress(&pWoCat, g_WoCat);
    cudaGetSymbolAddress(&pbcat,  g_bcat);

    cudaFuncSetAttribute(attn_kernel, cudaFuncAttributeMaxDynamicSharedMemorySize,
                         SM_TOTAL_FLOATS * 4);

    // K0: pack weights
    pack_weights<<<96, 256>>>(Wq0, Wkv0, Wo0, bo0, Wq1, Wkv1, Wo1, bo1);

    // K1: QKV projection for BOTH passes: [131072,128] @ [128,768]
    sgemm_kernel<<<dim3(6, 1024), 256>>>(x, (const float*)pWcat, (float*)pQKV,
                                         768, 128, nullptr);

    // K2: attention, both passes
    attn_kernel<<<dim3(1024, 8, 2), 256, SM_TOTAL_FLOATS * 4>>>(
        (const float*)pQKV, (float*)pO);

    // K3: output projection + bias + pass-sum: [131072,256] @ [256,128]
    sgemm_kernel<<<dim3(1, 1024), 256>>>((const float*)pO, (const float*)pWoCat,
                                         out, 128, 256, (const float*)pbcat);
}

// round 8
// speedup vs baseline: 2.1305x; 2.1305x over previous
#include <cuda_runtime.h>
#include <cstddef>

#define NTOK (8*128*128)   // 131072 tokens

// ---------------- scratch (static device memory: allocation-free) ----------------
__device__ float g_QKV[(size_t)NTOK * 768];   // [tok][ q0|k0|v0 | q1|k1|v1 ]
__device__ float g_O  [(size_t)NTOK * 256];   // [tok][ o0(128) | o1(128) ]
__device__ float g_Wcat [128 * 768];          // [k][ Wq0|Wk0|Wv0|Wq1|Wk1|Wv1 ]
__device__ float g_WoCat[256 * 128];          // [ Wo0 ; Wo1 ]
__device__ float g_bcat [128];                // bo0 + bo1

// ---------------- helpers ----------------
__device__ __forceinline__ unsigned f2tf32(float x) {
    unsigned r;
    asm("cvt.rna.tf32.f32 %0, %1;" : "=r"(r) : "f"(x));
    return r;
}

__device__ __forceinline__ void mma_tf32(float* d, const unsigned* a, const unsigned* b) {
    asm volatile(
        "mma.sync.aligned.m16n8k8.row.col.f32.tf32.tf32.f32 "
        "{%0,%1,%2,%3}, {%4,%5,%6,%7}, {%8,%9}, {%0,%1,%2,%3};"
        : "+f"(d[0]), "+f"(d[1]), "+f"(d[2]), "+f"(d[3])
        : "r"(a[0]), "r"(a[1]), "r"(a[2]), "r"(a[3]),
          "r"(b[0]), "r"(b[1]));
}

// ---------------- K0: pack weights ----------------
__global__ void pack_weights(const float* __restrict__ Wq0, const float* __restrict__ Wkv0,
                             const float* __restrict__ Wo0, const float* __restrict__ bo0,
                             const float* __restrict__ Wq1, const float* __restrict__ Wkv1,
                             const float* __restrict__ Wo1, const float* __restrict__ bo1) {
    const int n1 = 128 * 768;
    const int n2 = 256 * 128;
    for (int idx = blockIdx.x * blockDim.x + threadIdx.x; idx < n1 + n2 + 128;
         idx += gridDim.x * blockDim.x) {
        if (idx < n1) {
            int r = idx / 768, c = idx % 768;
            float v;
            if (c < 128)      v = Wq0 [r * 128 + c];
            else if (c < 384) v = Wkv0[r * 256 + (c - 128)];
            else if (c < 512) v = Wq1 [r * 128 + (c - 384)];
            else              v = Wkv1[r * 256 + (c - 512)];
            g_Wcat[idx] = v;
        } else if (idx < n1 + n2) {
            int j = idx - n1;
            int r = j / 128, c = j % 128;
            g_WoCat[j] = (r < 128) ? Wo0[r * 128 + c] : Wo1[(r - 128) * 128 + c];
        } else {
            int c = idx - n1 - n2;
            g_bcat[c] = bo0[c] + bo1[c];
        }
    }
}

// ---------------- TF32 tensor-core GEMM: C[M,N] = A[M,K] @ B[K,N] (+bias) ----------------
// Block tile 128x128, BK=32, 256 threads = 8 warps (4 along M x 2 along N).
// Warp tile 32x64 -> 2 m-frags x 8 n-frags of m16n8k8.
// As[128][36]/Bs[32][136]: fragment loads provably bank-conflict-free.
__global__ __launch_bounds__(256)
void sgemm_tf32(const float* __restrict__ A, const float* __restrict__ B,
                float* __restrict__ C, int N, int K, const float* __restrict__ bias) {
    __shared__ __align__(16) unsigned As[128][36];
    __shared__ __align__(16) unsigned Bs[32][136];

    const int t    = threadIdx.x;
    const int lane = t & 31;
    const int w    = t >> 5;
    const int warpM = w & 3;     // 0..3 -> 32 rows each
    const int warpN = w >> 2;    // 0..1 -> 64 cols each
    const int gid  = lane >> 2;  // 0..7
    const int tig  = lane & 3;   // 0..3
    const int nt = blockIdx.x, mt = blockIdx.y;

    const float* Ag = A + (size_t)mt * 128 * K;
    const float* Bg = B + (size_t)nt * 128;

    float acc[2][8][4];
    #pragma unroll
    for (int mf = 0; mf < 2; mf++)
        #pragma unroll
        for (int nf = 0; nf < 8; nf++)
            #pragma unroll
            for (int i = 0; i < 4; i++) acc[mf][nf][i] = 0.f;

    for (int k0 = 0; k0 < K; k0 += 32) {
        // A chunk 128x32 -> As (tf32-converted)
        #pragma unroll
        for (int l = 0; l < 4; l++) {
            int idx = t + l * 256;            // 0..1023
            int r  = idx >> 3;                // 0..127
            int c4 = (idx & 7) * 4;           // 0,4,..,28
            float4 v = *(const float4*)(Ag + (size_t)r * K + k0 + c4);
            uint4 u = make_uint4(f2tf32(v.x), f2tf32(v.y), f2tf32(v.z), f2tf32(v.w));
            *(uint4*)&As[r][c4] = u;
        }
        // B chunk 32x128 -> Bs (tf32-converted)
        #pragma unroll
        for (int l = 0; l < 4; l++) {
            int idx = t + l * 256;
            int r  = idx >> 5;                // 0..31
            int c4 = (idx & 31) * 4;          // 0,4,..,124
            float4 v = *(const float4*)(Bg + (size_t)(k0 + r) * N + c4);
            uint4 u = make_uint4(f2tf32(v.x), f2tf32(v.y), f2tf32(v.z), f2tf32(v.w));
            *(uint4*)&Bs[r][c4] = u;
        }
        __syncthreads();

        #pragma unroll
        for (int ks = 0; ks < 4; ks++) {
            const int kk = ks * 8;
            unsigned af[2][4];
            #pragma unroll
            for (int mf = 0; mf < 2; mf++) {
                int r0 = warpM * 32 + mf * 16 + gid;
                af[mf][0] = As[r0    ][kk + tig];
                af[mf][1] = As[r0 + 8][kk + tig];
                af[mf][2] = As[r0    ][kk + tig + 4];
                af[mf][3] = As[r0 + 8][kk + tig + 4];
            }
            unsigned bf[8][2];
            #pragma unroll
            for (int nf = 0; nf < 8; nf++) {
                int bn = warpN * 64 + nf * 8 + gid;
                bf[nf][0] = Bs[kk + tig    ][bn];
                bf[nf][1] = Bs[kk + tig + 4][bn];
            }
            #pragma unroll
            for (int mf = 0; mf < 2; mf++)
                #pragma unroll
                for (int nf = 0; nf < 8; nf++)
                    mma_tf32(acc[mf][nf], af[mf], bf[nf]);
        }
        __syncthreads();
    }

    // epilogue: each thread owns rows (gid, gid+8) x cols 2*tig,2*tig+1 per tile
    #pragma unroll
    for (int mf = 0; mf < 2; mf++) {
        size_t r0 = (size_t)mt * 128 + warpM * 32 + mf * 16 + gid;
        size_t r1 = r0 + 8;
        #pragma unroll
        for (int nf = 0; nf < 8; nf++) {
            int c = nt * 128 + warpN * 64 + nf * 8 + 2 * tig;
            float b0 = bias ? bias[c]     : 0.f;
            float b1 = bias ? bias[c + 1] : 0.f;
            *(float2*)(C + r0 * N + c) = make_float2(acc[mf][nf][0] + b0, acc[mf][nf][1] + b1);
            *(float2*)(C + r1 * N + c) = make_float2(acc[mf][nf][2] + b0, acc[mf][nf][3] + b1);
        }
    }
}

// ---------------- K2: tf32 tensor-core attention per (sequence, head, pass) ----------------
// grid (1024, 8, 2), 256 threads = 8 warps; warp w owns score rows [16w, 16w+16).
// Dynamic smem floats: QS[128][20] | KS[128][20] | VS[128][24] | PS[128][132]
// (PS rows hold the full 128-wide P matrix; stride 132 => conflict-free A-frag reloads)
#define ATT_QS 0
#define ATT_KS (128*20)
#define ATT_VS (2*128*20)
#define ATT_PS (2*128*20 + 128*24)
#define ATT_TOTAL_FLOATS (ATT_PS + 128*132)   // 25088 floats = 100352 B

__global__ __launch_bounds__(256)
void attn_tf32(const float* __restrict__ QKV, float* __restrict__ O) {
    extern __shared__ __align__(16) float sm[];
    float* QS = sm + ATT_QS;
    float* KS = sm + ATT_KS;
    float* VS = sm + ATT_VS;
    float* PS = sm + ATT_PS;

    const int t = threadIdx.x;
    const int s = blockIdx.x;     // sequence id (b*128 + other-axis)
    const int h = blockIdx.y;     // head
    const int p = blockIdx.z;     // pass: 0 = attend along H, 1 = attend along W
    const int b = s >> 7, sw = s & 127;
    const int coff = p * 384 + h * 16;

    // ---- load q, k, v (each 128x16, row-major) ----
    #pragma unroll
    for (int l = 0; l < 2; l++) {
        int idx = t + l * 256;            // 0..511
        int r  = idx >> 2;                // token 0..127
        int c4 = (idx & 3) * 4;           // 0,4,8,12
        size_t tok = p ? ((size_t)s * 128 + r)
                       : ((size_t)b * 16384 + (size_t)r * 128 + sw);
        const float* base = QKV + tok * 768 + coff;
        *(float4*)&QS[r * 20 + c4] = *(const float4*)(base + c4);
        *(float4*)&KS[r * 20 + c4] = *(const float4*)(base + 128 + c4);
        *(float4*)&VS[r * 24 + c4] = *(const float4*)(base + 256 + c4);
    }
    __syncthreads();

    const int lane = t & 31, w = t >> 5;
    const int gid = lane >> 2, tig = lane & 3;
    const int m0 = w * 16;
    const int rA = m0 + gid, rB = m0 + gid + 8;

    // ---- S = Q K^T : 16 n-frags x 2 k-chunks of m16n8k8 ----
    float acc[16][4];
    #pragma unroll
    for (int nf = 0; nf < 16; nf++)
        #pragma unroll
        for (int i = 0; i < 4; i++) acc[nf][i] = 0.f;

    #pragma unroll
    for (int kc = 0; kc < 2; kc++) {
        const int kk = kc * 8;
        unsigned af[4];
        af[0] = __float_as_uint(QS[rA * 20 + kk + tig]);
        af[1] = __float_as_uint(QS[rB * 20 + kk + tig]);
        af[2] = __float_as_uint(QS[rA * 20 + kk + tig + 4]);
        af[3] = __float_as_uint(QS[rB * 20 + kk + tig + 4]);
        #pragma unroll
        for (int nf = 0; nf < 16; nf++) {
            unsigned bf[2];
            bf[0] = __float_as_uint(KS[(nf * 8 + gid) * 20 + kk + tig]);
            bf[1] = __float_as_uint(KS[(nf * 8 + gid) * 20 + kk + tig + 4]);
            mma_tf32(acc[nf], af, bf);
        }
    }

    // ---- softmax (rows rA, rB live in this quad; shfl_xor 1,2 completes rows) ----
    float mx0 = -1e30f, mx1 = -1e30f;
    #pragma unroll
    for (int nf = 0; nf < 16; nf++) {
        #pragma unroll
        for (int i = 0; i < 4; i++) acc[nf][i] *= 0.25f;   // e^-0.5, e=16
        mx0 = fmaxf(mx0, fmaxf(acc[nf][0], acc[nf][1]));
        mx1 = fmaxf(mx1, fmaxf(acc[nf][2], acc[nf][3]));
    }
    mx0 = fmaxf(mx0, __shfl_xor_sync(0xffffffffu, mx0, 1));
    mx0 = fmaxf(mx0, __shfl_xor_sync(0xffffffffu, mx0, 2));
    mx1 = fmaxf(mx1, __shfl_xor_sync(0xffffffffu, mx1, 1));
    mx1 = fmaxf(mx1, __shfl_xor_sync(0xffffffffu, mx1, 2));

    float s0 = 0.f, s1 = 0.f;
    #pragma unroll
    for (int nf = 0; nf < 16; nf++) {
        float e0 = __expf(acc[nf][0] - mx0);
        float e1 = __expf(acc[nf][1] - mx0);
        float e2 = __expf(acc[nf][2] - mx1);
        float e3 = __expf(acc[nf][3] - mx1);
        acc[nf][0] = e0; acc[nf][1] = e1; acc[nf][2] = e2; acc[nf][3] = e3;
        s0 += e0 + e1; s1 += e2 + e3;
    }
    s0 += __shfl_xor_sync(0xffffffffu, s0, 1);
    s0 += __shfl_xor_sync(0xffffffffu, s0, 2);
    s1 += __shfl_xor_sync(0xffffffffu, s1, 1);
    s1 += __shfl_xor_sync(0xffffffffu, s1, 2);

    // ---- stage unnormalized P in smem (warp-private rows) ----
    #pragma unroll
    for (int nf = 0; nf < 16; nf++) {
        *(float2*)&PS[rA * 132 + nf * 8 + 2 * tig] = make_float2(acc[nf][0], acc[nf][1]);
        *(float2*)&PS[rB * 132 + nf * 8 + 2 * tig] = make_float2(acc[nf][2], acc[nf][3]);
    }
    __syncwarp();

    // ---- O = P V : 2 n-frags x 16 k-chunks ----
    float oacc[2][4] = {{0.f,0.f,0.f,0.f},{0.f,0.f,0.f,0.f}};
    #pragma unroll
    for (int kc = 0; kc < 16; kc++) {
        const int kk = kc * 8;
        unsigned af[4];
        af[0] = __float_as_uint(PS[rA * 132 + kk + tig]);
        af[1] = __float_as_uint(PS[rB * 132 + kk + tig]);
        af[2] = __float_as_uint(PS[rA * 132 + kk + tig + 4]);
        af[3] = __float_as_uint(PS[rB * 132 + kk + tig + 4]);
        #pragma unroll
        for (int nfr = 0; nfr < 2; nfr++) {
            unsigned bf[2];
            bf[0] = __float_as_uint(VS[(kk + tig) * 24 + nfr * 8 + gid]);
            bf[1] = __float_as_uint(VS[(kk + tig + 4) * 24 + nfr * 8 + gid]);
            mma_tf32(oacc[nfr], af, bf);
        }
    }

    const float inv0 = 1.f / s0, inv1 = 1.f / s1;
    size_t tokA = p ? ((size_t)s * 128 + rA)
                    : ((size_t)b * 16384 + (size_t)rA * 128 + sw);
    size_t tokB = tokA + (p ? 8 : 8 * 128);
    const int ocol = p * 128 + h * 16 + 2 * tig;
    #pragma unroll
    for (int nfr = 0; nfr < 2; nfr++) {
        *(float2*)(O + tokA * 256 + ocol + nfr * 8) =
            make_float2(oacc[nfr][0] * inv0, oacc[nfr][1] * inv0);
        *(float2*)(O + tokB * 256 + ocol + nfr * 8) =
            make_float2(oacc[nfr][2] * inv1, oacc[nfr][3] * inv1);
    }
}

// ---------------- launch ----------------
extern "C" void kernel_launch(void* const* d_in, const int* in_sizes, int n_in,
                              void* d_out, int out_size) {
    const float* x    = (const float*)d_in[0];
    const float* Wq0  = (const float*)d_in[1];
    const float* Wkv0 = (const float*)d_in[2];
    const float* Wo0  = (const float*)d_in[3];
    const float* bo0  = (const float*)d_in[4];
    const float* Wq1  = (const float*)d_in[5];
    const float* Wkv1 = (const float*)d_in[6];
    const float* Wo1  = (const float*)d_in[7];
    const float* bo1  = (const float*)d_in[8];
    float* out = (float*)d_out;

    void *pQKV, *pO, *pWcat, *pWoCat, *pbcat;
    cudaGetSymbolAddress(&pQKV,   g_QKV);
    cudaGetSymbolAddress(&pO,     g_O);
    cudaGetSymbolAddress(&pWcat,  g_Wcat);
    cudaGetSymbolAddress(&pWoCat, g_WoCat);
    cudaGetSymbolAddress(&pbcat,  g_bcat);

    cudaFuncSetAttribute(attn_tf32, cudaFuncAttributeMaxDynamicSharedMemorySize,
                         ATT_TOTAL_FLOATS * 4);

    // K0: pack weights
    pack_weights<<<96, 256>>>(Wq0, Wkv0, Wo0, bo0, Wq1, Wkv1, Wo1, bo1);

    // K1: QKV projection for BOTH passes (tf32 tensor cores): [131072,128] @ [128,768]
    sgemm_tf32<<<dim3(6, 1024), 256>>>(x, (const float*)pWcat, (float*)pQKV,
                                       768, 128, nullptr);

    // K2: attention, both passes (tf32 tensor cores)
    attn_tf32<<<dim3(1024, 8, 2), 256, ATT_TOTAL_FLOATS * 4>>>(
        (const float*)pQKV, (float*)pO);

    // K3: output projection + bias + pass-sum (tf32): [131072,256] @ [256,128]
    sgemm_tf32<<<dim3(1, 1024), 256>>>((const float*)pO, (const float*)pWoCat,
                                       out, 128, 256, (const float*)pbcat);
}